// round 7
// baseline (speedup 1.0000x reference)
#include <cuda_runtime.h>
#include <cuda_fp16.h>
#include <math.h>

#define NN 1024
#define CC 64
#define NITERS 20
#define LSCALE 0.001f
#define MV_BLOCKS 64
#define MV_ROWS 16

// ---------------- device globals (no cudaMalloc allowed) ----------------
__device__ float  g_psT[CC * NN];   // transposed softmax of y_s[7]  [C][N]
__device__ float  g_ptT[CC * NN];   // transposed softmax of y_t[7]  [C][N]
__device__ float  g_W  [NN * NN];   // fp32 cost matrix (loss precision)
__device__ __half g_Kh [NN * NN];   // fp16 K  (row-major)
__device__ __half g_KTh[NN * NN];   // fp16 K^T (row-major)
__device__ float  g_u[NN];
__device__ float  g_v[NN];
__device__ float  g_partial[MV_BLOCKS];
__device__ unsigned g_lcnt;         // loss completion counter (self-resetting)

// ---------------- PDL primitives ----------------
__device__ __forceinline__ void pdl_wait() {
    asm volatile("griddepcontrol.wait;" ::: "memory");
}
__device__ __forceinline__ void pdl_signal() {
    asm volatile("griddepcontrol.launch_dependents;" ::: "memory");
}

// ---------------- reductions ----------------
__device__ __forceinline__ float warp_sum(float v) {
#pragma unroll
    for (int o = 16; o > 0; o >>= 1) v += __shfl_down_sync(0xffffffffu, v, o);
    return v;
}
__device__ __forceinline__ float warp_max(float v) {
#pragma unroll
    for (int o = 16; o > 0; o >>= 1) v = fmaxf(v, __shfl_down_sync(0xffffffffu, v, o));
    return v;
}

__device__ __forceinline__ unsigned h2u(float a, float b) {
    __half2 h = __floats2half2_rn(a, b);
    return *reinterpret_cast<unsigned*>(&h);
}
__device__ __forceinline__ float2 u2f(unsigned u) {
    return __half22float2(*reinterpret_cast<__half2*>(&u));
}

// ======================= softmax (64 ch x 2 tensors) =======================
__global__ __launch_bounds__(256) void softmax_kernel(const float* __restrict__ ys,
                                                      const float* __restrict__ yt) {
    __shared__ float sc[9];
    int c = blockIdx.x;
    const float* y = (blockIdx.y == 0) ? ys : yt;
    float* pT      = (blockIdx.y == 0) ? g_psT : g_ptT;
    const float* base = y + 7 * NN * CC;
    int t = threadIdx.x;

    float vals[4];
    float mx = -3.4e38f;
#pragma unroll
    for (int k = 0; k < 4; k++) {
        vals[k] = base[(t + k * 256) * CC + c] * 0.5f;   // y/T, T=2
        mx = fmaxf(mx, vals[k]);
    }
    mx = warp_max(mx);
    if ((t & 31) == 0) sc[t >> 5] = mx;
    __syncthreads();
    if (t == 0) {
        float r = -3.4e38f;
#pragma unroll
        for (int i = 0; i < 8; i++) r = fmaxf(r, sc[i]);
        sc[8] = r;
    }
    __syncthreads();
    mx = sc[8];
    __syncthreads();

    float s = 0.f;
#pragma unroll
    for (int k = 0; k < 4; k++) { vals[k] = expf(vals[k] - mx); s += vals[k]; }
    s = warp_sum(s);
    if ((t & 31) == 0) sc[t >> 5] = s;
    __syncthreads();
    if (t == 0) {
        float r = 0.f;
#pragma unroll
        for (int i = 0; i < 8; i++) r += sc[i];
        sc[8] = r;
    }
    __syncthreads();
    float inv = 1.0f / sc[8];
#pragma unroll
    for (int k = 0; k < 4; k++) pT[c * NN + t + k * 256] = vals[k] * inv;
    __syncthreads();
    pdl_signal();
}

// ==== W/K build (128 blocks x 8 rows): W fp32, K fp16 + K^T fp16, u1 fused ====
__global__ __launch_bounds__(256) void wk_kernel() {
    __shared__ float sPS[8 * CC];
    __shared__ float red[8][8];
    int b = blockIdx.x, t = threadIdx.x;
    int i0 = b * 8;

    pdl_wait();   // needs softmax outputs (immediate predecessor)

    for (int idx = t; idx < 8 * CC; idx += 256) {
        int i = idx >> 6, c = idx & 63;
        sPS[idx] = g_psT[c * NN + i0 + i];
    }
    __syncthreads();

    const unsigned long long SMASK = 0x8000000080000000ULL;
    const unsigned long long AMASK = 0x7FFFFFFF7FFFFFFFULL;
    unsigned long long acc0[8], acc1[8];
#pragma unroll
    for (int i = 0; i < 8; i++) { acc0[i] = 0ULL; acc1[i] = 0ULL; }

    int j0 = t * 4;
    for (int c = 0; c < CC; c++) {
        ulonglong2 bv = *(const ulonglong2*)&g_ptT[c * NN + j0];
        unsigned long long nb0 = bv.x ^ SMASK;
        unsigned long long nb1 = bv.y ^ SMASK;
#pragma unroll
        for (int i = 0; i < 8; i++) {
            unsigned ai = __float_as_uint(sPS[i * CC + c]);
            unsigned long long aa, d0, d1;
            asm("mov.b64 %0, {%1, %1};" : "=l"(aa) : "r"(ai));
            asm("add.rn.f32x2 %0, %1, %2;" : "=l"(d0) : "l"(aa), "l"(nb0));
            asm("add.rn.f32x2 %0, %1, %2;" : "=l"(d1) : "l"(aa), "l"(nb1));
            d0 &= AMASK;
            d1 &= AMASK;
            asm("add.rn.f32x2 %0, %0, %1;" : "+l"(acc0[i]) : "l"(d0));
            asm("add.rn.f32x2 %0, %0, %1;" : "+l"(acc1[i]) : "l"(d1));
        }
    }

    float kvf[8][4];
    float rsum[8];
#pragma unroll
    for (int i = 0; i < 8; i++) {
        unsigned x0, x1, x2, x3;
        asm("mov.b64 {%0, %1}, %2;" : "=r"(x0), "=r"(x1) : "l"(acc0[i]));
        asm("mov.b64 {%0, %1}, %2;" : "=r"(x2), "=r"(x3) : "l"(acc1[i]));
        float4 wv = make_float4(__uint_as_float(x0), __uint_as_float(x1),
                                __uint_as_float(x2), __uint_as_float(x3));
        kvf[i][0] = __expf(-10.0f * wv.x);
        kvf[i][1] = __expf(-10.0f * wv.y);
        kvf[i][2] = __expf(-10.0f * wv.z);
        kvf[i][3] = __expf(-10.0f * wv.w);
        *(float4*)&g_W[(size_t)(i0 + i) * NN + j0] = wv;
        // fp16 row store
        uint2 r2;
        r2.x = h2u(kvf[i][0], kvf[i][1]);
        r2.y = h2u(kvf[i][2], kvf[i][3]);
        *(uint2*)&g_Kh[(size_t)(i0 + i) * NN + j0] = r2;
        rsum[i] = kvf[i][0] + kvf[i][1] + kvf[i][2] + kvf[i][3];
    }
    // fp16 K^T stores: column j gets 8 consecutive rows = 16 contiguous bytes
#pragma unroll
    for (int q = 0; q < 4; q++) {
        uint4 c4;
        c4.x = h2u(kvf[0][q], kvf[1][q]);
        c4.y = h2u(kvf[2][q], kvf[3][q]);
        c4.z = h2u(kvf[4][q], kvf[5][q]);
        c4.w = h2u(kvf[6][q], kvf[7][q]);
        *(uint4*)&g_KTh[(size_t)(j0 + q) * NN + i0] = c4;
    }

    // fused first u-step: u1 = 1 / rowsum(K)  (v == 1)
    int w = t >> 5, l = t & 31;
#pragma unroll
    for (int i = 0; i < 8; i++) {
        float s = warp_sum(rsum[i]);
        if (l == 0) red[i][w] = s;
    }
    __syncthreads();
    if (t < 8) {
        float s = 0.f;
#pragma unroll
        for (int k = 0; k < 8; k++) s += red[t][k];
        g_u[i0 + t] = 1.0f / s;
    }
    __syncthreads();
    pdl_signal();
}

// ========== fp16 matvec: vout = 1/(M . vin), 64 blocks x 16 rows ==========
// Warp w handles rows 2w, 2w+1. Lane l covers columns [32l, 32l+32).
// M prefetched before pdl_wait when stable (written >=2 nodes back).
__global__ __launch_bounds__(256) void matvec_kernel(const __half* __restrict__ M,
                                                     const float* __restrict__ vin,
                                                     float* __restrict__ vout,
                                                     int wait_first) {
    int b = blockIdx.x, t = threadIdx.x, w = t >> 5, l = t & 31;
    int row0 = b * MV_ROWS + 2 * w;
    const uint4* A = (const uint4*)(M + (size_t)row0 * NN) + 4 * l;
    const uint4* B = A + NN / 8;

    if (wait_first) pdl_wait();
    uint4 ka[4], kb[4];
#pragma unroll
    for (int i = 0; i < 4; i++) { ka[i] = __ldcg(A + i); kb[i] = __ldcg(B + i); }
    if (!wait_first) pdl_wait();

    const float4* V = (const float4*)vin + 8 * l;
    float4 vf[8];
#pragma unroll
    for (int i = 0; i < 8; i++) vf[i] = __ldcg(V + i);

    float s0 = 0.f, s1 = 0.f;
#pragma unroll
    for (int i = 0; i < 4; i++) {
        float2 a0 = u2f(ka[i].x), a1 = u2f(ka[i].y), a2 = u2f(ka[i].z), a3 = u2f(ka[i].w);
        float2 b0 = u2f(kb[i].x), b1 = u2f(kb[i].y), b2 = u2f(kb[i].z), b3 = u2f(kb[i].w);
        float4 v0 = vf[2 * i], v1 = vf[2 * i + 1];
        s0 += a0.x * v0.x + a0.y * v0.y + a1.x * v0.z + a1.y * v0.w
            + a2.x * v1.x + a2.y * v1.y + a3.x * v1.z + a3.y * v1.w;
        s1 += b0.x * v0.x + b0.y * v0.y + b1.x * v0.z + b1.y * v0.w
            + b2.x * v1.x + b2.y * v1.y + b3.x * v1.z + b3.y * v1.w;
    }
    s0 = warp_sum(s0);
    s1 = warp_sum(s1);
    if (l == 0) {
        vout[row0]     = 1.0f / s0;
        vout[row0 + 1] = 1.0f / s1;
    }
    pdl_signal();
}

// ==== loss (single node): sum_ij u_i K_ij v_j W_ij, fence+counter finale ====
__global__ __launch_bounds__(256) void loss_kernel(float* __restrict__ out) {
    __shared__ float red[8];
    __shared__ int sLast;
    __shared__ float s2[2];
    int b = blockIdx.x, t = threadIdx.x, w = t >> 5, l = t & 31;
    int row0 = b * MV_ROWS + 2 * w;

    pdl_wait();

    const float4* V = (const float4*)g_v + 8 * l;
    float4 vf[8];
#pragma unroll
    for (int i = 0; i < 8; i++) vf[i] = __ldcg(V + i);

    float u0 = __ldcg(&g_u[row0]);
    float u1 = __ldcg(&g_u[row0 + 1]);

    float s0 = 0.f, s1 = 0.f;
#pragma unroll
    for (int r = 0; r < 2; r++) {
        int row = row0 + r;
        const uint4*  Kp = (const uint4*)(g_Kh + (size_t)row * NN) + 4 * l;
        const float4* Wp = (const float4*)(g_W + (size_t)row * NN) + 8 * l;
        float s = 0.f;
#pragma unroll
        for (int i = 0; i < 4; i++) {
            uint4 kq = __ldcg(Kp + i);
            float2 c0 = u2f(kq.x), c1 = u2f(kq.y), c2 = u2f(kq.z), c3 = u2f(kq.w);
            float4 w0 = __ldcg(Wp + 2 * i);
            float4 w1 = __ldcg(Wp + 2 * i + 1);
            float4 v0 = vf[2 * i], v1 = vf[2 * i + 1];
            s += c0.x * w0.x * v0.x + c0.y * w0.y * v0.y
               + c1.x * w0.z * v0.z + c1.y * w0.w * v0.w
               + c2.x * w1.x * v1.x + c2.y * w1.y * v1.y
               + c3.x * w1.z * v1.z + c3.y * w1.w * v1.w;
        }
        if (r == 0) s0 = s; else s1 = s;
    }
    s0 = warp_sum(s0);
    s1 = warp_sum(s1);
    if (l == 0) red[w] = s0 * u0 + s1 * u1;
    __syncthreads();

    if (t == 0) {
        float p = 0.f;
#pragma unroll
        for (int i = 0; i < 8; i++) p += red[i];
        g_partial[b] = p;
        __threadfence();
        unsigned old = atomicAdd(&g_lcnt, 1u);
        sLast = (old == MV_BLOCKS - 1) ? 1 : 0;
    }
    __syncthreads();

    if (sLast) {
        __threadfence();
        float p = (t < MV_BLOCKS) ? __ldcg(&g_partial[t]) : 0.f;
        if (t < 64) {
            p = warp_sum(p);
            if (l == 0) s2[w] = p;
        }
        __syncthreads();
        if (t == 0) {
            out[0] = LSCALE * (s2[0] + s2[1]);
            g_lcnt = 0;   // reset for next replay (all blocks already arrived)
        }
    }
}

// ---------------- host: PDL launches on the legacy stream ----------------
static void launch_pdl(const void* func, dim3 grid, dim3 block, void** args) {
    cudaLaunchConfig_t cfg = {};
    cfg.gridDim = grid;
    cfg.blockDim = block;
    cfg.dynamicSmemBytes = 0;
    cfg.stream = 0;
    cudaLaunchAttribute attr[1];
    attr[0].id = cudaLaunchAttributeProgrammaticStreamSerialization;
    attr[0].val.programmaticStreamSerializationAllowed = 1;
    cfg.attrs = attr;
    cfg.numAttrs = 1;
    cudaLaunchKernelExC(&cfg, func, args);
}

extern "C" void kernel_launch(void* const* d_in, const int* in_sizes, int n_in,
                              void* d_out, int out_size) {
    const float* ys = (const float*)d_in[0];
    const float* yt = (const float*)d_in[1];
    float* out = (float*)d_out;

    {   // softmax
        void* args[] = {(void*)&ys, (void*)&yt};
        launch_pdl((const void*)softmax_kernel, dim3(64, 2), dim3(256), args);
    }
    {   // W fp32 + K/KT fp16 build + u1
        void* args[] = {};
        launch_pdl((const void*)wk_kernel, dim3(128), dim3(256), args);
    }

    static __half *pKh = nullptr, *pKTh = nullptr;
    static float *pU = nullptr, *pV = nullptr;
    if (!pKh) {
        cudaGetSymbolAddress((void**)&pKh,  g_Kh);
        cudaGetSymbolAddress((void**)&pKTh, g_KTh);
        cudaGetSymbolAddress((void**)&pU,   g_u);
        cudaGetSymbolAddress((void**)&pV,   g_v);
    }

    for (int it = 0; it < NITERS; it++) {
        {   // v = 1/(KT u); first node's M (KTh) comes from immediate predecessor
            int wf = (it == 0) ? 1 : 0;
            void* args[] = {(void*)&pKTh, (void*)&pU, (void*)&pV, (void*)&wf};
            launch_pdl((const void*)matvec_kernel, dim3(MV_BLOCKS), dim3(256), args);
        }
        if (it < NITERS - 1) {   // u = 1/(K v)
            int wf = 0;
            void* args[] = {(void*)&pKh, (void*)&pV, (void*)&pU, (void*)&wf};
            launch_pdl((const void*)matvec_kernel, dim3(MV_BLOCKS), dim3(256), args);
        }
    }

    {   // fused loss (partials + fence/counter final reduce)
        void* args[] = {(void*)&out};
        launch_pdl((const void*)loss_kernel, dim3(MV_BLOCKS), dim3(256), args);
    }
}

// round 8
// speedup vs baseline: 1.8448x; 1.8448x over previous
#include <cuda_runtime.h>
#include <math.h>

#define NN 1024
#define CC 64
#define NITERS 20
#define LSCALE 0.001f
#define IB 32      // iteration-node blocks
#define IR 32      // KT rows per iteration block

// ---------------- device globals (no cudaMalloc allowed) ----------------
__device__ float g_psT[CC * NN];   // transposed softmax of y_s[7]  [C][N]
__device__ float g_ptT[CC * NN];   // transposed softmax of y_t[7]  [C][N]
__device__ float g_W [NN * NN];
__device__ float g_K [NN * NN];
__device__ float g_KT[NN * NN];
__device__ float g_u [NN];
__device__ float g_v [NN];
__device__ float g_part[(NITERS - 1) * IB * NN];   // per-iter per-block partials
__device__ float g_partial[128];

// ---------------- PDL primitives ----------------
__device__ __forceinline__ void pdl_wait() {
    asm volatile("griddepcontrol.wait;" ::: "memory");
}
__device__ __forceinline__ void pdl_signal() {
    asm volatile("griddepcontrol.launch_dependents;" ::: "memory");
}

// ---------------- reductions ----------------
__device__ __forceinline__ float warp_sum(float v) {
#pragma unroll
    for (int o = 16; o > 0; o >>= 1) v += __shfl_down_sync(0xffffffffu, v, o);
    return v;
}
__device__ __forceinline__ float warp_max(float v) {
#pragma unroll
    for (int o = 16; o > 0; o >>= 1) v = fmaxf(v, __shfl_down_sync(0xffffffffu, v, o));
    return v;
}

// ======================= softmax (64 ch x 2 tensors) =======================
__global__ __launch_bounds__(256) void softmax_kernel(const float* __restrict__ ys,
                                                      const float* __restrict__ yt) {
    __shared__ float sc[9];
    int c = blockIdx.x;
    const float* y = (blockIdx.y == 0) ? ys : yt;
    float* pT      = (blockIdx.y == 0) ? g_psT : g_ptT;
    const float* base = y + 7 * NN * CC;
    int t = threadIdx.x;

    float vals[4];
    float mx = -3.4e38f;
#pragma unroll
    for (int k = 0; k < 4; k++) {
        vals[k] = base[(t + k * 256) * CC + c] * 0.5f;   // y/T, T=2
        mx = fmaxf(mx, vals[k]);
    }
    mx = warp_max(mx);
    if ((t & 31) == 0) sc[t >> 5] = mx;
    __syncthreads();
    if (t == 0) {
        float r = -3.4e38f;
#pragma unroll
        for (int i = 0; i < 8; i++) r = fmaxf(r, sc[i]);
        sc[8] = r;
    }
    __syncthreads();
    mx = sc[8];
    __syncthreads();

    float s = 0.f;
#pragma unroll
    for (int k = 0; k < 4; k++) { vals[k] = expf(vals[k] - mx); s += vals[k]; }
    s = warp_sum(s);
    if ((t & 31) == 0) sc[t >> 5] = s;
    __syncthreads();
    if (t == 0) {
        float r = 0.f;
#pragma unroll
        for (int i = 0; i < 8; i++) r += sc[i];
        sc[8] = r;
    }
    __syncthreads();
    float inv = 1.0f / sc[8];
#pragma unroll
    for (int k = 0; k < 4; k++) pT[c * NN + t + k * 256] = vals[k] * inv;
    __syncthreads();
    pdl_signal();
}

// ==== W/K build (128 blocks x 8 rows): W + K + KT directly, u1 fused ====
__global__ __launch_bounds__(256) void wk_kernel() {
    __shared__ float sPS[8 * CC];
    __shared__ float red[8][8];
    int b = blockIdx.x, t = threadIdx.x;
    int i0 = b * 8;

    pdl_wait();   // needs softmax outputs (immediate predecessor)

    for (int idx = t; idx < 8 * CC; idx += 256) {
        int i = idx >> 6, c = idx & 63;
        sPS[idx] = g_psT[c * NN + i0 + i];
    }
    __syncthreads();

    const unsigned long long SMASK = 0x8000000080000000ULL;
    const unsigned long long AMASK = 0x7FFFFFFF7FFFFFFFULL;
    unsigned long long acc0[8], acc1[8];
#pragma unroll
    for (int i = 0; i < 8; i++) { acc0[i] = 0ULL; acc1[i] = 0ULL; }

    int j0 = t * 4;
    for (int c = 0; c < CC; c++) {
        ulonglong2 bv = *(const ulonglong2*)&g_ptT[c * NN + j0];
        unsigned long long nb0 = bv.x ^ SMASK;
        unsigned long long nb1 = bv.y ^ SMASK;
#pragma unroll
        for (int i = 0; i < 8; i++) {
            unsigned ai = __float_as_uint(sPS[i * CC + c]);
            unsigned long long aa, d0, d1;
            asm("mov.b64 %0, {%1, %1};" : "=l"(aa) : "r"(ai));
            asm("add.rn.f32x2 %0, %1, %2;" : "=l"(d0) : "l"(aa), "l"(nb0));
            asm("add.rn.f32x2 %0, %1, %2;" : "=l"(d1) : "l"(aa), "l"(nb1));
            d0 &= AMASK;
            d1 &= AMASK;
            asm("add.rn.f32x2 %0, %0, %1;" : "+l"(acc0[i]) : "l"(d0));
            asm("add.rn.f32x2 %0, %0, %1;" : "+l"(acc1[i]) : "l"(d1));
        }
    }

    float kvf[8][4];
    float rsum[8];
#pragma unroll
    for (int i = 0; i < 8; i++) {
        unsigned x0, x1, x2, x3;
        asm("mov.b64 {%0, %1}, %2;" : "=r"(x0), "=r"(x1) : "l"(acc0[i]));
        asm("mov.b64 {%0, %1}, %2;" : "=r"(x2), "=r"(x3) : "l"(acc1[i]));
        float4 wv = make_float4(__uint_as_float(x0), __uint_as_float(x1),
                                __uint_as_float(x2), __uint_as_float(x3));
        kvf[i][0] = __expf(-10.0f * wv.x);
        kvf[i][1] = __expf(-10.0f * wv.y);
        kvf[i][2] = __expf(-10.0f * wv.z);
        kvf[i][3] = __expf(-10.0f * wv.w);
        *(float4*)&g_W[(size_t)(i0 + i) * NN + j0] =
            make_float4(wv.x, wv.y, wv.z, wv.w);
        *(float4*)&g_K[(size_t)(i0 + i) * NN + j0] =
            make_float4(kvf[i][0], kvf[i][1], kvf[i][2], kvf[i][3]);
        rsum[i] = kvf[i][0] + kvf[i][1] + kvf[i][2] + kvf[i][3];
    }
    // KT direct: row (j0+q), cols i0..i0+7
#pragma unroll
    for (int q = 0; q < 4; q++) {
        *(float4*)&g_KT[(size_t)(j0 + q) * NN + i0] =
            make_float4(kvf[0][q], kvf[1][q], kvf[2][q], kvf[3][q]);
        *(float4*)&g_KT[(size_t)(j0 + q) * NN + i0 + 4] =
            make_float4(kvf[4][q], kvf[5][q], kvf[6][q], kvf[7][q]);
    }

    // fused first u-step: u1 = 1 / rowsum(K)  (v == 1)
    int w = t >> 5, l = t & 31;
#pragma unroll
    for (int i = 0; i < 8; i++) {
        float s = warp_sum(rsum[i]);
        if (l == 0) red[i][w] = s;
    }
    __syncthreads();
    if (t < 8) {
        float s = 0.f;
#pragma unroll
        for (int k = 0; k < 8; k++) s += red[t][k];
        g_u[i0 + t] = 1.0f / s;
    }
    __syncthreads();
    pdl_signal();
}

// ============ one full Sinkhorn iteration per node ============
// Block b owns KT rows [32b, 32b+32) in smem.
//   1) assemble u (from partials, or direct g_u on iter 1)
//   2) v_j = 1/(KT[j] . u) for its 32 rows
//   3) emit part'[b][i] = sum_{j in b} KT[j][i] * v_j   (iters 1..19)
//      or publish g_u / g_v                              (iter 20)
__global__ __launch_bounds__(256) void iter_kernel(const float* __restrict__ pin,
                                                   float* __restrict__ pout,
                                                   int wait_first, int direct_in,
                                                   int emit) {
    extern __shared__ float sm[];
    float* sKT = sm;                 // IR * NN
    float* sU  = sm + IR * NN;       // NN
    float* sV  = sU + NN;            // IR

    int b = blockIdx.x, t = threadIdx.x, w = t >> 5, l = t & 31;
    int i0 = b * IR;
    const float4* src = (const float4*)(g_KT + (size_t)i0 * NN);
    float4* dstKT = (float4*)sKT;

    if (wait_first) pdl_wait();
    // stage 32 KT rows (stable data) — overlaps predecessor tail when !wait_first
#pragma unroll
    for (int k = 0; k < IR * NN / 4 / 256; k++)
        dstKT[t + k * 256] = __ldcg(src + t + k * 256);
    if (!wait_first) pdl_wait();

    // assemble u into sU (fixed-order sum over blocks -> deterministic)
    if (direct_in) {
        ((float4*)sU)[t] = __ldcg((const float4*)pin + t);
    } else {
        const float4* P = (const float4*)pin;
        float4 a = make_float4(0.f, 0.f, 0.f, 0.f);
#pragma unroll
        for (int bb = 0; bb < IB; bb++) {
            float4 p = __ldcg(P + bb * (NN / 4) + t);
            a.x += p.x; a.y += p.y; a.z += p.z; a.w += p.w;
        }
        ((float4*)sU)[t] = make_float4(1.f / a.x, 1.f / a.y, 1.f / a.z, 1.f / a.w);
    }
    __syncthreads();

    // v-dots: warp w handles rows 4w..4w+3, 4 accumulators in flight
    {
        const float4* K0 = (const float4*)(sKT + (4 * w + 0) * NN);
        const float4* K1 = (const float4*)(sKT + (4 * w + 1) * NN);
        const float4* K2 = (const float4*)(sKT + (4 * w + 2) * NN);
        const float4* K3 = (const float4*)(sKT + (4 * w + 3) * NN);
        const float4* U4 = (const float4*)sU;
        float s0 = 0.f, s1 = 0.f, s2 = 0.f, s3 = 0.f;
#pragma unroll
        for (int i = 0; i < 8; i++) {
            int idx = l + 32 * i;      // consecutive lanes -> consecutive float4
            float4 uq = U4[idx];
            float4 a = K0[idx], c = K1[idx], d = K2[idx], e = K3[idx];
            s0 += a.x * uq.x + a.y * uq.y + a.z * uq.z + a.w * uq.w;
            s1 += c.x * uq.x + c.y * uq.y + c.z * uq.z + c.w * uq.w;
            s2 += d.x * uq.x + d.y * uq.y + d.z * uq.z + d.w * uq.w;
            s3 += e.x * uq.x + e.y * uq.y + e.z * uq.z + e.w * uq.w;
        }
        s0 = warp_sum(s0); s1 = warp_sum(s1);
        s2 = warp_sum(s2); s3 = warp_sum(s3);
        if (l == 0) {
            sV[4 * w + 0] = 1.f / s0;
            sV[4 * w + 1] = 1.f / s1;
            sV[4 * w + 2] = 1.f / s2;
            sV[4 * w + 3] = 1.f / s3;
        }
    }
    __syncthreads();

    if (emit) {
        // rank-32 update: pout[b][i] = sum_r sKT[r][i] * sV[r]
        float4 acc = make_float4(0.f, 0.f, 0.f, 0.f);
#pragma unroll
        for (int r = 0; r < IR; r++) {
            float vr = sV[r];                                   // broadcast
            float4 kq = ((const float4*)(sKT + r * NN))[t];     // conflict-free
            acc.x += kq.x * vr; acc.y += kq.y * vr;
            acc.z += kq.z * vr; acc.w += kq.w * vr;
        }
        ((float4*)pout)[b * (NN / 4) + t] = acc;
    } else {
        // final iteration: publish u20 and v20 for the loss node
        if (t < IR) {
            g_v[i0 + t] = sV[t];
            g_u[i0 + t] = sU[i0 + t];
        }
    }
    __syncthreads();
    pdl_signal();
}

// ============ loss partials: sum_ij u_i K_ij v_j W_ij over 8 rows ============
__global__ __launch_bounds__(256) void loss_partial_kernel() {
    __shared__ float sc[9];
    int b = blockIdx.x, t = threadIdx.x;
    int i0 = b * 8;
    const float4* Kr = (const float4*)(g_K + (size_t)i0 * NN);
    const float4* Wr = (const float4*)(g_W + (size_t)i0 * NN);

    // prefetch stable K and W rows before the wait
    float4 km[8], wm[8];
#pragma unroll
    for (int r = 0; r < 8; r++) {
        km[r] = __ldcg(Kr + r * 256 + t);
        wm[r] = __ldcg(Wr + r * 256 + t);
    }
    pdl_wait();   // u, v (immediate predecessor) become safe

    float4 v = __ldcg(((const float4*)g_v) + t);
    float s = 0.f;
#pragma unroll
    for (int r = 0; r < 8; r++) {
        float ur = __ldcg(&g_u[i0 + r]);
        s += ur * (km[r].x * wm[r].x * v.x + km[r].y * wm[r].y * v.y
                 + km[r].z * wm[r].z * v.z + km[r].w * wm[r].w * v.w);
    }
    s = warp_sum(s);
    if ((t & 31) == 0) sc[t >> 5] = s;
    __syncthreads();
    if (t == 0) {
        float r = 0.f;
#pragma unroll
        for (int i = 0; i < 8; i++) r += sc[i];
        g_partial[b] = r;
    }
    __syncthreads();
    pdl_signal();
}

__global__ __launch_bounds__(128) void loss_final_kernel(float* __restrict__ out) {
    __shared__ float sc[4];
    int t = threadIdx.x;
    pdl_wait();
    float s = __ldcg(&g_partial[t]);
    s = warp_sum(s);
    if ((t & 31) == 0) sc[t >> 5] = s;
    __syncthreads();
    if (t == 0) {
        float r = sc[0] + sc[1] + sc[2] + sc[3];
        out[0] = LSCALE * r;
    }
}

// ---------------- host: PDL launches on the legacy stream ----------------
static void launch_pdl(const void* func, dim3 grid, dim3 block, void** args,
                       size_t smem = 0) {
    cudaLaunchConfig_t cfg = {};
    cfg.gridDim = grid;
    cfg.blockDim = block;
    cfg.dynamicSmemBytes = smem;
    cfg.stream = 0;
    cudaLaunchAttribute attr[1];
    attr[0].id = cudaLaunchAttributeProgrammaticStreamSerialization;
    attr[0].val.programmaticStreamSerializationAllowed = 1;
    cfg.attrs = attr;
    cfg.numAttrs = 1;
    cudaLaunchKernelExC(&cfg, func, args);
}

#define SMEM_ITER ((IR * NN + NN + IR) * (int)sizeof(float))

extern "C" void kernel_launch(void* const* d_in, const int* in_sizes, int n_in,
                              void* d_out, int out_size) {
    const float* ys = (const float*)d_in[0];
    const float* yt = (const float*)d_in[1];
    float* out = (float*)d_out;

    static float *pU = nullptr, *pPart = nullptr;
    static bool init = false;
    if (!init) {
        cudaGetSymbolAddress((void**)&pU,    g_u);
        cudaGetSymbolAddress((void**)&pPart, g_part);
        cudaFuncSetAttribute(iter_kernel,
                             cudaFuncAttributeMaxDynamicSharedMemorySize, SMEM_ITER);
        init = true;
    }

    {   // softmax
        void* args[] = {(void*)&ys, (void*)&yt};
        launch_pdl((const void*)softmax_kernel, dim3(64, 2), dim3(256), args);
    }
    {   // W + K + KT build + u1
        void* args[] = {};
        launch_pdl((const void*)wk_kernel, dim3(128), dim3(256), args);
    }

    for (int k = 1; k <= NITERS; k++) {
        const float* pin = (k == 1) ? pU : (pPart + (size_t)(k - 2) * IB * NN);
        float* pout = (k < NITERS) ? (pPart + (size_t)(k - 1) * IB * NN) : pU;
        int wait_first = (k == 1) ? 1 : 0;     // KT written by immediate pred (wk)
        int direct_in  = (k == 1) ? 1 : 0;
        int emit       = (k < NITERS) ? 1 : 0;
        void* args[] = {(void*)&pin, (void*)&pout,
                        (void*)&wait_first, (void*)&direct_in, (void*)&emit};
        launch_pdl((const void*)iter_kernel, dim3(IB), dim3(256), args, SMEM_ITER);
    }

    {   // loss partials
        void* args[] = {};
        launch_pdl((const void*)loss_partial_kernel, dim3(128), dim3(256), args);
    }
    {   // final reduce
        void* args[] = {(void*)&out};
        launch_pdl((const void*)loss_final_kernel, dim3(1), dim3(128), args);
    }
}

// round 9
// speedup vs baseline: 2.9768x; 1.6136x over previous
#include <cuda_runtime.h>
#include <math.h>

#define NN 1024
#define CC 64
#define NITERS 20
#define LSCALE 0.001f
#define MV_BLOCKS 128
#define MV_ROWS 8

// ---------------- device globals (no cudaMalloc allowed) ----------------
__device__ float g_psT[CC * NN];   // transposed softmax of y_s[7]  [C][N]
__device__ float g_ptT[CC * NN];   // transposed softmax of y_t[7]  [C][N]
__device__ float g_W [NN * NN];
__device__ float g_K [NN * NN];
__device__ float g_KT[NN * NN];
__device__ float g_u [NN];
__device__ float g_v [NN];
__device__ float g_partial[MV_BLOCKS];

// ---------------- PDL primitives ----------------
__device__ __forceinline__ void pdl_wait() {
    asm volatile("griddepcontrol.wait;" ::: "memory");
}
__device__ __forceinline__ void pdl_signal() {
    asm volatile("griddepcontrol.launch_dependents;" ::: "memory");
}

// ---------------- reductions ----------------
__device__ __forceinline__ float warp_sum(float v) {
#pragma unroll
    for (int o = 16; o > 0; o >>= 1) v += __shfl_down_sync(0xffffffffu, v, o);
    return v;
}
__device__ __forceinline__ float warp_max(float v) {
#pragma unroll
    for (int o = 16; o > 0; o >>= 1) v = fmaxf(v, __shfl_down_sync(0xffffffffu, v, o));
    return v;
}

// ======================= softmax (64 ch x 2 tensors) =======================
__global__ __launch_bounds__(256) void softmax_kernel(const float* __restrict__ ys,
                                                      const float* __restrict__ yt) {
    __shared__ float sc[9];
    int c = blockIdx.x;
    const float* y = (blockIdx.y == 0) ? ys : yt;
    float* pT      = (blockIdx.y == 0) ? g_psT : g_ptT;
    const float* base = y + 7 * NN * CC;
    int t = threadIdx.x;

    float vals[4];
    float mx = -3.4e38f;
#pragma unroll
    for (int k = 0; k < 4; k++) {
        vals[k] = base[(t + k * 256) * CC + c] * 0.5f;   // y/T, T=2
        mx = fmaxf(mx, vals[k]);
    }
    mx = warp_max(mx);
    if ((t & 31) == 0) sc[t >> 5] = mx;
    __syncthreads();
    if (t == 0) {
        float r = -3.4e38f;
#pragma unroll
        for (int i = 0; i < 8; i++) r = fmaxf(r, sc[i]);
        sc[8] = r;
    }
    __syncthreads();
    mx = sc[8];
    __syncthreads();

    float s = 0.f;
#pragma unroll
    for (int k = 0; k < 4; k++) { vals[k] = expf(vals[k] - mx); s += vals[k]; }
    s = warp_sum(s);
    if ((t & 31) == 0) sc[t >> 5] = s;
    __syncthreads();
    if (t == 0) {
        float r = 0.f;
#pragma unroll
        for (int i = 0; i < 8; i++) r += sc[i];
        sc[8] = r;
    }
    __syncthreads();
    float inv = 1.0f / sc[8];
#pragma unroll
    for (int k = 0; k < 4; k++) pT[c * NN + t + k * 256] = vals[k] * inv;
    __syncthreads();
    pdl_signal();   // end-signal: successor (wk) must start after our stores
}

// ==== W/K build (128 blocks x 8 rows): W + K + KT direct, u1 fused ====
__global__ __launch_bounds__(256) void wk_kernel() {
    __shared__ float sPS[8 * CC];
    __shared__ float red[8][8];
    int b = blockIdx.x, t = threadIdx.x;
    int i0 = b * 8;

    pdl_wait();   // needs softmax outputs (immediate predecessor)

    for (int idx = t; idx < 8 * CC; idx += 256) {
        int i = idx >> 6, c = idx & 63;
        sPS[idx] = g_psT[c * NN + i0 + i];
    }
    __syncthreads();

    const unsigned long long SMASK = 0x8000000080000000ULL;
    const unsigned long long AMASK = 0x7FFFFFFF7FFFFFFFULL;
    unsigned long long acc0[8], acc1[8];
#pragma unroll
    for (int i = 0; i < 8; i++) { acc0[i] = 0ULL; acc1[i] = 0ULL; }

    int j0 = t * 4;
    for (int c = 0; c < CC; c++) {
        ulonglong2 bv = *(const ulonglong2*)&g_ptT[c * NN + j0];
        unsigned long long nb0 = bv.x ^ SMASK;
        unsigned long long nb1 = bv.y ^ SMASK;
#pragma unroll
        for (int i = 0; i < 8; i++) {
            unsigned ai = __float_as_uint(sPS[i * CC + c]);
            unsigned long long aa, d0, d1;
            asm("mov.b64 %0, {%1, %1};" : "=l"(aa) : "r"(ai));
            asm("add.rn.f32x2 %0, %1, %2;" : "=l"(d0) : "l"(aa), "l"(nb0));
            asm("add.rn.f32x2 %0, %1, %2;" : "=l"(d1) : "l"(aa), "l"(nb1));
            d0 &= AMASK;
            d1 &= AMASK;
            asm("add.rn.f32x2 %0, %0, %1;" : "+l"(acc0[i]) : "l"(d0));
            asm("add.rn.f32x2 %0, %0, %1;" : "+l"(acc1[i]) : "l"(d1));
        }
    }

    float kvf[8][4];
    float rsum[8];
#pragma unroll
    for (int i = 0; i < 8; i++) {
        unsigned x0, x1, x2, x3;
        asm("mov.b64 {%0, %1}, %2;" : "=r"(x0), "=r"(x1) : "l"(acc0[i]));
        asm("mov.b64 {%0, %1}, %2;" : "=r"(x2), "=r"(x3) : "l"(acc1[i]));
        float4 wv = make_float4(__uint_as_float(x0), __uint_as_float(x1),
                                __uint_as_float(x2), __uint_as_float(x3));
        kvf[i][0] = __expf(-10.0f * wv.x);
        kvf[i][1] = __expf(-10.0f * wv.y);
        kvf[i][2] = __expf(-10.0f * wv.z);
        kvf[i][3] = __expf(-10.0f * wv.w);
        *(float4*)&g_W[(size_t)(i0 + i) * NN + j0] = wv;
        *(float4*)&g_K[(size_t)(i0 + i) * NN + j0] =
            make_float4(kvf[i][0], kvf[i][1], kvf[i][2], kvf[i][3]);
        rsum[i] = kvf[i][0] + kvf[i][1] + kvf[i][2] + kvf[i][3];
    }
    // KT direct: row (j0+q), cols i0..i0+7
#pragma unroll
    for (int q = 0; q < 4; q++) {
        *(float4*)&g_KT[(size_t)(j0 + q) * NN + i0] =
            make_float4(kvf[0][q], kvf[1][q], kvf[2][q], kvf[3][q]);
        *(float4*)&g_KT[(size_t)(j0 + q) * NN + i0 + 4] =
            make_float4(kvf[4][q], kvf[5][q], kvf[6][q], kvf[7][q]);
    }

    // fused first u-step: u1 = 1 / rowsum(K)  (v == 1)
    int w = t >> 5, l = t & 31;
#pragma unroll
    for (int i = 0; i < 8; i++) {
        float s = warp_sum(rsum[i]);
        if (l == 0) red[i][w] = s;
    }
    __syncthreads();
    if (t < 8) {
        float s = 0.f;
#pragma unroll
        for (int k = 0; k < 8; k++) s += red[t][k];
        g_u[i0 + t] = 1.0f / s;
    }
    __syncthreads();
    pdl_signal();   // end-signal: successor prefetches KT we just wrote
}

// ================ Sinkhorn half-step matvec: vout = 1/(M . vin) ================
// M (K or KT) is WRITE-ONCE -> successors' prefetches never touch our output,
// so we can signal at kernel start and fully hide the successor's launch ramp.
// wait_first=1 only for the first matvec (KT written by immediate pred wk):
// there the signal moves after the wait so the successor launches only once
// wk is fully flushed.
__global__ __launch_bounds__(256) void matvec_kernel(const float* __restrict__ M,
                                                     const float* __restrict__ vin,
                                                     float* __restrict__ vout,
                                                     int wait_first) {
    __shared__ float red[MV_ROWS][8];
    int b = blockIdx.x, t = threadIdx.x;
    const float4* Mr = (const float4*)(M + (size_t)b * MV_ROWS * NN);

    float4 m[MV_ROWS];
    if (wait_first) {
        pdl_wait();
        pdl_signal();
#pragma unroll
        for (int r = 0; r < MV_ROWS; r++) m[r] = __ldcg(Mr + r * 256 + t);
    } else {
        pdl_signal();                      // release successor immediately
#pragma unroll
        for (int r = 0; r < MV_ROWS; r++) m[r] = __ldcg(Mr + r * 256 + t);
        pdl_wait();                        // vin becomes safe
    }

    float4 v = __ldcg(((const float4*)vin) + t);
    int w = t >> 5, l = t & 31;
#pragma unroll
    for (int r = 0; r < MV_ROWS; r++) {
        float s = m[r].x * v.x + m[r].y * v.y + m[r].z * v.z + m[r].w * v.w;
        s = warp_sum(s);
        if (l == 0) red[r][w] = s;
    }
    __syncthreads();
    if (t < MV_ROWS) {
        float s = 0.f;
#pragma unroll
        for (int k = 0; k < 8; k++) s += red[t][k];
        vout[b * MV_ROWS + t] = 1.0f / s;
    }
}

// ============ loss partials: sum_ij u_i K_ij v_j W_ij over 8 rows ============
__global__ __launch_bounds__(256) void loss_partial_kernel() {
    __shared__ float sc[9];
    int b = blockIdx.x, t = threadIdx.x;
    int i0 = b * MV_ROWS;
    const float4* Kr = (const float4*)(g_K + (size_t)i0 * NN);
    const float4* Wr = (const float4*)(g_W + (size_t)i0 * NN);

    pdl_signal();   // successor (loss_final) reads g_partial only post-wait

    // prefetch stable K and W rows before the wait
    float4 km[MV_ROWS], wm[MV_ROWS];
#pragma unroll
    for (int r = 0; r < MV_ROWS; r++) {
        km[r] = __ldcg(Kr + r * 256 + t);
        wm[r] = __ldcg(Wr + r * 256 + t);
    }
    pdl_wait();   // u, v (immediate predecessor) become safe

    float4 v = __ldcg(((const float4*)g_v) + t);
    float s = 0.f;
#pragma unroll
    for (int r = 0; r < MV_ROWS; r++) {
        float ur = __ldcg(&g_u[i0 + r]);
        s += ur * (km[r].x * wm[r].x * v.x + km[r].y * wm[r].y * v.y
                 + km[r].z * wm[r].z * v.z + km[r].w * wm[r].w * v.w);
    }
    s = warp_sum(s);
    if ((t & 31) == 0) sc[t >> 5] = s;
    __syncthreads();
    if (t == 0) {
        float r = 0.f;
#pragma unroll
        for (int i = 0; i < 8; i++) r += sc[i];
        g_partial[b] = r;
    }
}

__global__ __launch_bounds__(128) void loss_final_kernel(float* __restrict__ out) {
    __shared__ float sc[4];
    int t = threadIdx.x;
    pdl_wait();
    float s = __ldcg(&g_partial[t]);
    s = warp_sum(s);
    if ((t & 31) == 0) sc[t >> 5] = s;
    __syncthreads();
    if (t == 0) {
        float r = sc[0] + sc[1] + sc[2] + sc[3];
        out[0] = LSCALE * r;
    }
}

// ---------------- host: PDL launches on the legacy stream ----------------
static void launch_pdl(const void* func, dim3 grid, dim3 block, void** args) {
    cudaLaunchConfig_t cfg = {};
    cfg.gridDim = grid;
    cfg.blockDim = block;
    cfg.dynamicSmemBytes = 0;
    cfg.stream = 0;
    cudaLaunchAttribute attr[1];
    attr[0].id = cudaLaunchAttributeProgrammaticStreamSerialization;
    attr[0].val.programmaticStreamSerializationAllowed = 1;
    cfg.attrs = attr;
    cfg.numAttrs = 1;
    cudaLaunchKernelExC(&cfg, func, args);
}

extern "C" void kernel_launch(void* const* d_in, const int* in_sizes, int n_in,
                              void* d_out, int out_size) {
    const float* ys = (const float*)d_in[0];
    const float* yt = (const float*)d_in[1];
    float* out = (float*)d_out;

    {   // softmax
        void* args[] = {(void*)&ys, (void*)&yt};
        launch_pdl((const void*)softmax_kernel, dim3(64, 2), dim3(256), args);
    }
    {   // W + K + KT build + u1 (transpose node eliminated)
        void* args[] = {};
        launch_pdl((const void*)wk_kernel, dim3(128), dim3(256), args);
    }

    static float *pK = nullptr, *pKT = nullptr, *pU = nullptr, *pV = nullptr;
    if (!pK) {
        cudaGetSymbolAddress((void**)&pK,  g_K);
        cudaGetSymbolAddress((void**)&pKT, g_KT);
        cudaGetSymbolAddress((void**)&pU,  g_u);
        cudaGetSymbolAddress((void**)&pV,  g_v);
    }

    for (int it = 0; it < NITERS; it++) {
        {   // v = 1/(KT u)
            int wf = (it == 0) ? 1 : 0;
            void* args[] = {(void*)&pKT, (void*)&pU, (void*)&pV, (void*)&wf};
            launch_pdl((const void*)matvec_kernel, dim3(MV_BLOCKS), dim3(256), args);
        }
        if (it < NITERS - 1) {   // u = 1/(K v)
            int wf = 0;
            void* args[] = {(void*)&pK, (void*)&pV, (void*)&pU, (void*)&wf};
            launch_pdl((const void*)matvec_kernel, dim3(MV_BLOCKS), dim3(256), args);
        }
    }

    {   // loss partials
        void* args[] = {};
        launch_pdl((const void*)loss_partial_kernel, dim3(128), dim3(256), args);
    }
    {   // final reduce
        void* args[] = {(void*)&out};
        launch_pdl((const void*)loss_final_kernel, dim3(1), dim3(128), args);
    }
}

// round 10
// speedup vs baseline: 3.3433x; 1.1231x over previous
#include <cuda_runtime.h>
#include <cuda_fp16.h>
#include <math.h>

#define NN 1024
#define CC 64
#define NITERS 20
#define LSCALE 0.001f
#define MV_BLOCKS 128
#define MV_ROWS 8

// ---------------- device globals (no cudaMalloc allowed) ----------------
__device__ float  g_psT[CC * NN];   // transposed softmax of y_s[7]  [C][N]
__device__ float  g_ptT[CC * NN];   // transposed softmax of y_t[7]  [C][N]
__device__ float  g_W  [NN * NN];   // fp32 cost matrix
__device__ __half g_Kh [NN * NN];   // fp16 K  (row-major)
__device__ __half g_KTh[NN * NN];   // fp16 K^T (row-major)
__device__ float  g_u [NN];
__device__ float  g_v [NN];
__device__ float  g_partial[MV_BLOCKS];

// ---------------- PDL primitives ----------------
__device__ __forceinline__ void pdl_wait() {
    asm volatile("griddepcontrol.wait;" ::: "memory");
}
__device__ __forceinline__ void pdl_signal() {
    asm volatile("griddepcontrol.launch_dependents;" ::: "memory");
}

// ---------------- reductions ----------------
__device__ __forceinline__ float warp_sum(float v) {
#pragma unroll
    for (int o = 16; o > 0; o >>= 1) v += __shfl_down_sync(0xffffffffu, v, o);
    return v;
}
__device__ __forceinline__ float warp_max(float v) {
#pragma unroll
    for (int o = 16; o > 0; o >>= 1) v = fmaxf(v, __shfl_down_sync(0xffffffffu, v, o));
    return v;
}

__device__ __forceinline__ unsigned h2u(float a, float b) {
    __half2 h = __floats2half2_rn(a, b);
    return *reinterpret_cast<unsigned*>(&h);
}
__device__ __forceinline__ float2 u2f(unsigned u) {
    return __half22float2(*reinterpret_cast<__half2*>(&u));
}

// ======================= softmax (64 ch x 2 tensors) =======================
__global__ __launch_bounds__(256) void softmax_kernel(const float* __restrict__ ys,
                                                      const float* __restrict__ yt) {
    __shared__ float sc[9];
    int c = blockIdx.x;
    const float* y = (blockIdx.y == 0) ? ys : yt;
    float* pT      = (blockIdx.y == 0) ? g_psT : g_ptT;
    const float* base = y + 7 * NN * CC;
    int t = threadIdx.x;

    float vals[4];
    float mx = -3.4e38f;
#pragma unroll
    for (int k = 0; k < 4; k++) {
        vals[k] = base[(t + k * 256) * CC + c] * 0.5f;   // y/T, T=2
        mx = fmaxf(mx, vals[k]);
    }
    mx = warp_max(mx);
    if ((t & 31) == 0) sc[t >> 5] = mx;
    __syncthreads();
    if (t == 0) {
        float r = -3.4e38f;
#pragma unroll
        for (int i = 0; i < 8; i++) r = fmaxf(r, sc[i]);
        sc[8] = r;
    }
    __syncthreads();
    mx = sc[8];
    __syncthreads();

    float s = 0.f;
#pragma unroll
    for (int k = 0; k < 4; k++) { vals[k] = expf(vals[k] - mx); s += vals[k]; }
    s = warp_sum(s);
    if ((t & 31) == 0) sc[t >> 5] = s;
    __syncthreads();
    if (t == 0) {
        float r = 0.f;
#pragma unroll
        for (int i = 0; i < 8; i++) r += sc[i];
        sc[8] = r;
    }
    __syncthreads();
    float inv = 1.0f / sc[8];
#pragma unroll
    for (int k = 0; k < 4; k++) pT[c * NN + t + k * 256] = vals[k] * inv;
    __syncthreads();
    pdl_signal();
}

// ==== W/K build (128 blocks x 8 rows): W fp32, K + KT fp16 direct, u1 fused ====
__global__ __launch_bounds__(256) void wk_kernel() {
    __shared__ float sPS[8 * CC];
    __shared__ float red[8][8];
    int b = blockIdx.x, t = threadIdx.x;
    int i0 = b * 8;

    pdl_wait();   // needs softmax outputs (immediate predecessor)

    for (int idx = t; idx < 8 * CC; idx += 256) {
        int i = idx >> 6, c = idx & 63;
        sPS[idx] = g_psT[c * NN + i0 + i];
    }
    __syncthreads();

    const unsigned long long SMASK = 0x8000000080000000ULL;
    const unsigned long long AMASK = 0x7FFFFFFF7FFFFFFFULL;
    unsigned long long acc0[8], acc1[8];
#pragma unroll
    for (int i = 0; i < 8; i++) { acc0[i] = 0ULL; acc1[i] = 0ULL; }

    int j0 = t * 4;
    for (int c = 0; c < CC; c++) {
        ulonglong2 bv = *(const ulonglong2*)&g_ptT[c * NN + j0];
        unsigned long long nb0 = bv.x ^ SMASK;
        unsigned long long nb1 = bv.y ^ SMASK;
#pragma unroll
        for (int i = 0; i < 8; i++) {
            unsigned ai = __float_as_uint(sPS[i * CC + c]);
            unsigned long long aa, d0, d1;
            asm("mov.b64 %0, {%1, %1};" : "=l"(aa) : "r"(ai));
            asm("add.rn.f32x2 %0, %1, %2;" : "=l"(d0) : "l"(aa), "l"(nb0));
            asm("add.rn.f32x2 %0, %1, %2;" : "=l"(d1) : "l"(aa), "l"(nb1));
            d0 &= AMASK;
            d1 &= AMASK;
            asm("add.rn.f32x2 %0, %0, %1;" : "+l"(acc0[i]) : "l"(d0));
            asm("add.rn.f32x2 %0, %0, %1;" : "+l"(acc1[i]) : "l"(d1));
        }
    }

    float kvf[8][4];
    float rsum[8];
#pragma unroll
    for (int i = 0; i < 8; i++) {
        unsigned x0, x1, x2, x3;
        asm("mov.b64 {%0, %1}, %2;" : "=r"(x0), "=r"(x1) : "l"(acc0[i]));
        asm("mov.b64 {%0, %1}, %2;" : "=r"(x2), "=r"(x3) : "l"(acc1[i]));
        float4 wv = make_float4(__uint_as_float(x0), __uint_as_float(x1),
                                __uint_as_float(x2), __uint_as_float(x3));
        kvf[i][0] = __expf(-10.0f * wv.x);
        kvf[i][1] = __expf(-10.0f * wv.y);
        kvf[i][2] = __expf(-10.0f * wv.z);
        kvf[i][3] = __expf(-10.0f * wv.w);
        *(float4*)&g_W[(size_t)(i0 + i) * NN + j0] = wv;
        uint2 r2;
        r2.x = h2u(kvf[i][0], kvf[i][1]);
        r2.y = h2u(kvf[i][2], kvf[i][3]);
        *(uint2*)&g_Kh[(size_t)(i0 + i) * NN + j0] = r2;
        rsum[i] = kvf[i][0] + kvf[i][1] + kvf[i][2] + kvf[i][3];
    }
    // fp16 KT direct: column j holds 8 consecutive rows = 16 contiguous bytes
#pragma unroll
    for (int q = 0; q < 4; q++) {
        uint4 c4;
        c4.x = h2u(kvf[0][q], kvf[1][q]);
        c4.y = h2u(kvf[2][q], kvf[3][q]);
        c4.z = h2u(kvf[4][q], kvf[5][q]);
        c4.w = h2u(kvf[6][q], kvf[7][q]);
        *(uint4*)&g_KTh[(size_t)(j0 + q) * NN + i0] = c4;
    }

    // fused first u-step: u1 = 1 / rowsum(K)  (v == 1)
    int w = t >> 5, l = t & 31;
#pragma unroll
    for (int i = 0; i < 8; i++) {
        float s = warp_sum(rsum[i]);
        if (l == 0) red[i][w] = s;
    }
    __syncthreads();
    if (t < 8) {
        float s = 0.f;
#pragma unroll
        for (int k = 0; k < 8; k++) s += red[t][k];
        g_u[i0 + t] = 1.0f / s;
    }
    __syncthreads();
    pdl_signal();
}

// ========= fp16 matvec: vout = 1/(M . vin), R6 structure (128 x 8 rows) =========
// Thread t covers cols [4t, 4t+4). M rows prefetched (uint2 = 4 halves) before
// pdl_wait when stable (written >= 2 nodes back).
__global__ __launch_bounds__(256) void matvec_kernel(const __half* __restrict__ M,
                                                     const float* __restrict__ vin,
                                                     float* __restrict__ vout,
                                                     int wait_first) {
    __shared__ float red[MV_ROWS][8];
    int b = blockIdx.x, t = threadIdx.x;
    const __half* Mb = M + (size_t)b * MV_ROWS * NN;

    if (wait_first) pdl_wait();
    uint2 m[MV_ROWS];
#pragma unroll
    for (int r = 0; r < MV_ROWS; r++)
        m[r] = __ldcg((const uint2*)(Mb + (size_t)r * NN) + t);
    if (!wait_first) pdl_wait();

    float4 v = __ldcg(((const float4*)vin) + t);
    int w = t >> 5, l = t & 31;
#pragma unroll
    for (int r = 0; r < MV_ROWS; r++) {
        float2 a0 = u2f(m[r].x), a1 = u2f(m[r].y);
        float s = a0.x * v.x + a0.y * v.y + a1.x * v.z + a1.y * v.w;
        s = warp_sum(s);
        if (l == 0) red[r][w] = s;
    }
    __syncthreads();
    if (t < MV_ROWS) {
        float s = 0.f;
#pragma unroll
        for (int k = 0; k < 8; k++) s += red[t][k];
        vout[b * MV_ROWS + t] = 1.0f / s;
    }
    __syncthreads();
    pdl_signal();
}

// ============ loss partials: sum_ij u_i K_ij v_j W_ij over 8 rows ============
__global__ __launch_bounds__(256) void loss_partial_kernel() {
    __shared__ float sc[9];
    int b = blockIdx.x, t = threadIdx.x;
    int i0 = b * MV_ROWS;
    const __half*  Kb = g_Kh + (size_t)i0 * NN;
    const float4*  Wr = (const float4*)(g_W + (size_t)i0 * NN);

    // prefetch stable K (fp16) and W rows before the wait
    uint2  km[MV_ROWS];
    float4 wm[MV_ROWS];
#pragma unroll
    for (int r = 0; r < MV_ROWS; r++) {
        km[r] = __ldcg((const uint2*)(Kb + (size_t)r * NN) + t);
        wm[r] = __ldcg(Wr + r * 256 + t);
    }
    pdl_wait();   // u, v (immediate predecessor) become safe

    float4 v = __ldcg(((const float4*)g_v) + t);
    float s = 0.f;
#pragma unroll
    for (int r = 0; r < MV_ROWS; r++) {
        float ur = __ldcg(&g_u[i0 + r]);
        float2 a0 = u2f(km[r].x), a1 = u2f(km[r].y);
        s += ur * (a0.x * wm[r].x * v.x + a0.y * wm[r].y * v.y
                 + a1.x * wm[r].z * v.z + a1.y * wm[r].w * v.w);
    }
    s = warp_sum(s);
    if ((t & 31) == 0) sc[t >> 5] = s;
    __syncthreads();
    if (t == 0) {
        float r = 0.f;
#pragma unroll
        for (int i = 0; i < 8; i++) r += sc[i];
        g_partial[b] = r;
    }
    __syncthreads();
    pdl_signal();
}

__global__ __launch_bounds__(128) void loss_final_kernel(float* __restrict__ out) {
    __shared__ float sc[4];
    int t = threadIdx.x;
    pdl_wait();
    float s = __ldcg(&g_partial[t]);
    s = warp_sum(s);
    if ((t & 31) == 0) sc[t >> 5] = s;
    __syncthreads();
    if (t == 0) {
        float r = sc[0] + sc[1] + sc[2] + sc[3];
        out[0] = LSCALE * r;
    }
}

// ---------------- host: PDL launches on the legacy stream ----------------
static void launch_pdl(const void* func, dim3 grid, dim3 block, void** args) {
    cudaLaunchConfig_t cfg = {};
    cfg.gridDim = grid;
    cfg.blockDim = block;
    cfg.dynamicSmemBytes = 0;
    cfg.stream = 0;
    cudaLaunchAttribute attr[1];
    attr[0].id = cudaLaunchAttributeProgrammaticStreamSerialization;
    attr[0].val.programmaticStreamSerializationAllowed = 1;
    cfg.attrs = attr;
    cfg.numAttrs = 1;
    cudaLaunchKernelExC(&cfg, func, args);
}

extern "C" void kernel_launch(void* const* d_in, const int* in_sizes, int n_in,
                              void* d_out, int out_size) {
    const float* ys = (const float*)d_in[0];
    const float* yt = (const float*)d_in[1];
    float* out = (float*)d_out;

    {   // softmax
        void* args[] = {(void*)&ys, (void*)&yt};
        launch_pdl((const void*)softmax_kernel, dim3(64, 2), dim3(256), args);
    }
    {   // W fp32 + K/KT fp16 direct + u1 (transpose node eliminated)
        void* args[] = {};
        launch_pdl((const void*)wk_kernel, dim3(128), dim3(256), args);
    }

    static __half *pKh = nullptr, *pKTh = nullptr;
    static float *pU = nullptr, *pV = nullptr;
    if (!pKh) {
        cudaGetSymbolAddress((void**)&pKh,  g_Kh);
        cudaGetSymbolAddress((void**)&pKTh, g_KTh);
        cudaGetSymbolAddress((void**)&pU,   g_u);
        cudaGetSymbolAddress((void**)&pV,   g_v);
    }

    for (int it = 0; it < NITERS; it++) {
        {   // v = 1/(KT u); first one waits before touching KT (written by wk)
            int wf = (it == 0) ? 1 : 0;
            void* args[] = {(void*)&pKTh, (void*)&pU, (void*)&pV, (void*)&wf};
            launch_pdl((const void*)matvec_kernel, dim3(MV_BLOCKS), dim3(256), args);
        }
        if (it < NITERS - 1) {   // u = 1/(K v)
            int wf = 0;
            void* args[] = {(void*)&pKh, (void*)&pV, (void*)&pU, (void*)&wf};
            launch_pdl((const void*)matvec_kernel, dim3(MV_BLOCKS), dim3(256), args);
        }
    }

    {   // loss partials
        void* args[] = {};
        launch_pdl((const void*)loss_partial_kernel, dim3(128), dim3(256), args);
    }
    {   // final reduce
        void* args[] = {(void*)&out};
        launch_pdl((const void*)loss_final_kernel, dim3(1), dim3(128), args);
    }
}